// round 6
// baseline (speedup 1.0000x reference)
#include <cuda_runtime.h>

#define D 64
#define MAXN 100000

// Scratch accumulator g[N, 64] (static __device__: no allocs allowed)
__device__ __align__(16) float g_scratch[MAXN * D];

// ---------------------------------------------------------------------------
// Scatter:  g[dst[e], :] += (ci[src[e]] * drop_mask[e]) * review_feat[e, :]
// Warp-cooperative (proven ~28us). Metadata coalesced once per warp; ballot
// skips the ~70% exact-zero dropout edges; 2 live edges per iteration,
// one coalesced LDG.128 + one red.global.add.v4.f32 each.
// ---------------------------------------------------------------------------
__global__ void scatter_kernel(const float4* __restrict__ rf,
                               const float*  __restrict__ ci,
                               const float*  __restrict__ dm,
                               const int*    __restrict__ src,
                               const int*    __restrict__ dst,
                               int E) {
    int warp = (blockIdx.x * blockDim.x + threadIdx.x) >> 5;
    int lane = threadIdx.x & 31;
    int ebase = warp * 32;
    int e = ebase + lane;

    float m = 0.f, s = 0.f;
    int d = 0;
    if (e < E) {
        m = dm[e];
        if (m != 0.f) {
            d = dst[e];
            s = ci[src[e]] * m;
        }
    }
    unsigned mask = __ballot_sync(0xFFFFFFFFu, m != 0.f);

    int half = lane >> 4;
    int q = lane & 15;

    while (mask) {
        int l0 = __ffs(mask) - 1; mask &= mask - 1;
        int l1 = -1;
        if (mask) { l1 = __ffs(mask) - 1; mask &= mask - 1; }

        int l = half ? l1 : l0;
        int lsafe = (l >= 0) ? l : l0;
        float sv = __shfl_sync(0xFFFFFFFFu, s, lsafe);
        int   dv = __shfl_sync(0xFFFFFFFFu, d, lsafe);

        if (l >= 0) {
            float4 v = rf[(size_t)(ebase + l) * 16 + q];
            v.x *= sv; v.y *= sv; v.z *= sv; v.w *= sv;
            float* p = &g_scratch[(size_t)dv * D + q * 4];
            asm volatile("red.global.add.v4.f32 [%0], {%1, %2, %3, %4};"
                         :: "l"(p), "f"(v.x), "f"(v.y), "f"(v.z), "f"(v.w)
                         : "memory");
        }
    }
}

// ---------------------------------------------------------------------------
// GEMM: out = (g @ W^T) * ci
// 128 threads/block, 128 rows x 64 feats per block; thread tile 8 rows x 8
// feats (fi = tid&7 -> feats fi*8..+7; ri = tid>>3 -> rows ri*8..+7).
// Inner loop over k-chunks of 4 (float4 LDS):
//   Gs[r][k] pad-68: phase lanes (0-7) share (ri,jr) -> broadcast, no conflict.
//   Ws[f][k] pad-68 with XOR chunk swizzle (kc ^ (f>>3)) -> conflict-free
//   across the 8 distinct f's in a phase.
// Per thread per k: 64B LDS -> 32 FMA2: crossbar/FMA tied -> ~FMA floor.
// ---------------------------------------------------------------------------
#define GS_PITCH 68
#define WS_PITCH 68

__global__ void __launch_bounds__(128, 3)
gemm_scale_kernel(const float* __restrict__ W,
                  const float* __restrict__ ci,
                  float* __restrict__ out,
                  int N) {
    extern __shared__ __align__(16) float sh[];
    float* Gs = sh;                         // [128][GS_PITCH]
    float* Ws = sh + 128 * GS_PITCH;        // [64][WS_PITCH], swizzled chunks

    int tid = threadIdx.x;                  // 128 threads
    int row0 = blockIdx.x * 128;

    // Load W with XOR chunk swizzle: chunk kc of row f stored at kc ^ (f>>3)
    #pragma unroll
    for (int i = tid; i < D * D; i += 128) {
        int f = i >> 6, k = i & 63;
        int kc = k >> 2;
        Ws[f * WS_PITCH + (((kc ^ (f >> 3)) & 15) << 2) + (k & 3)] = W[i];
    }
    // Load G tile [128][64] (zero-pad past N); coalesced LDG, conflict-free STS
    #pragma unroll
    for (int i = tid; i < 128 * D; i += 128) {
        int r = i >> 6, k = i & 63;
        int row = row0 + r;
        Gs[r * GS_PITCH + k] = (row < N) ? g_scratch[(size_t)row * D + k] : 0.f;
    }
    __syncthreads();

    int fi = tid & 7;           // feats fi*8 .. fi*8+7
    int ri = tid >> 3;          // rows  ri*8 .. ri*8+7

    // acc[jr][p]: row jr (0..7), feature-pair p (0..3), f32x2 packed
    unsigned long long acc[8][4];
    #pragma unroll
    for (int jr = 0; jr < 8; jr++)
        #pragma unroll
        for (int p = 0; p < 4; p++) acc[jr][p] = 0ull;

    const float* gbase = &Gs[ri * 8 * GS_PITCH];
    const float* wbase = &Ws[fi * 8 * WS_PITCH];

    #pragma unroll
    for (int kc = 0; kc < 16; kc++) {
        int sw = ((kc ^ fi) & 15) << 2;     // swizzled chunk offset for this thread
        float4 g4[8], w4[8];
        #pragma unroll
        for (int j = 0; j < 8; j++) {
            g4[j] = *reinterpret_cast<const float4*>(gbase + j * GS_PITCH + (kc << 2));
            w4[j] = *reinterpret_cast<const float4*>(wbase + j * WS_PITCH + sw);
        }
        #pragma unroll
        for (int kk = 0; kk < 4; kk++) {
            float wv[8];
            #pragma unroll
            for (int j = 0; j < 8; j++)
                wv[j] = (kk == 0) ? w4[j].x : (kk == 1) ? w4[j].y
                      : (kk == 2) ? w4[j].z : w4[j].w;
            unsigned long long wp[4];
            #pragma unroll
            for (int p = 0; p < 4; p++)
                asm("mov.b64 %0, {%1, %2};" : "=l"(wp[p])
                    : "f"(wv[2 * p]), "f"(wv[2 * p + 1]));
            #pragma unroll
            for (int jr = 0; jr < 8; jr++) {
                float gv = (kk == 0) ? g4[jr].x : (kk == 1) ? g4[jr].y
                         : (kk == 2) ? g4[jr].z : g4[jr].w;
                unsigned long long g2;
                asm("mov.b64 %0, {%1, %1};" : "=l"(g2) : "f"(gv));
                #pragma unroll
                for (int p = 0; p < 4; p++)
                    asm("fma.rn.f32x2 %0, %1, %2, %0;"
                        : "+l"(acc[jr][p]) : "l"(g2), "l"(wp[p]));
            }
        }
    }

    // Epilogue: scale by ci[row], two STG.128 per row (feats fi*8..+7)
    #pragma unroll
    for (int jr = 0; jr < 8; jr++) {
        int row = row0 + ri * 8 + jr;
        if (row < N) {
            float c = ci[row];
            unsigned long long c2;
            asm("mov.b64 %0, {%1, %1};" : "=l"(c2) : "f"(c));
            float2 o[4];
            #pragma unroll
            for (int p = 0; p < 4; p++) {
                unsigned long long rp;
                asm("mul.rn.f32x2 %0, %1, %2;" : "=l"(rp) : "l"(acc[jr][p]), "l"(c2));
                o[p] = *reinterpret_cast<float2*>(&rp);
            }
            float4* op = reinterpret_cast<float4*>(&out[(size_t)row * D + fi * 8]);
            op[0] = make_float4(o[0].x, o[0].y, o[1].x, o[1].y);
            op[1] = make_float4(o[2].x, o[2].y, o[3].x, o[3].y);
        }
    }
}

// ---------------------------------------------------------------------------
// Launch
// Inputs: review_feat [E,64] f32, ci [N,1] f32, W [64,64] f32,
//         drop_mask [E,1] f32, src [E] i32, dst [E] i32.  Output: [N,64] f32
// ---------------------------------------------------------------------------
extern "C" void kernel_launch(void* const* d_in, const int* in_sizes, int n_in,
                              void* d_out, int out_size) {
    const float4* rf  = (const float4*)d_in[0];
    const float*  ci  = (const float*) d_in[1];
    const float*  W   = (const float*) d_in[2];
    const float*  dm  = (const float*) d_in[3];
    const int*    src = (const int*)   d_in[4];
    const int*    dst = (const int*)   d_in[5];
    float* out = (float*)d_out;

    int E = in_sizes[4];
    int N = in_sizes[1];

    // 1. zero scratch accumulator (graph-capturable memset node)
    void* gptr = nullptr;
    cudaGetSymbolAddress(&gptr, g_scratch);
    cudaMemsetAsync(gptr, 0, (size_t)N * D * sizeof(float), 0);

    // 2. warp-cooperative scatter-accumulate (dropout-sparse, REDG.v4)
    int warps = (E + 31) / 32;
    int sblocks = (warps * 32 + 255) / 256;
    scatter_kernel<<<sblocks, 256>>>(rf, ci, dm, src, dst, E);

    // 3. GEMM by W^T fused with final ci scale (8x8 register tile, f32x2)
    int smem = (128 * GS_PITCH + 64 * WS_PITCH) * sizeof(float);
    cudaFuncSetAttribute(gemm_scale_kernel,
                         cudaFuncAttributeMaxDynamicSharedMemorySize, smem);
    gemm_scale_kernel<<<(N + 127) / 128, 128, smem>>>(W, ci, out, N);
}

// round 12
// speedup vs baseline: 1.4929x; 1.4929x over previous
#include <cuda_runtime.h>
#include <cuda_bf16.h>
#include <cstdint>

#define D 64
#define MAXN 100000

// Scratch accumulator g[N, 64] (static __device__: no allocs allowed)
__device__ __align__(16) float g_scratch[MAXN * D];

// ---------------------------------------------------------------------------
// Scatter:  g[dst[e], :] += (ci[src[e]] * drop_mask[e]) * review_feat[e, :]
// Warp-cooperative (proven ~28us): coalesced metadata, ballot skips the ~70%
// exact-zero dropout edges, 2 live edges/iter, LDG.128 + red.global.add.v4.
// ---------------------------------------------------------------------------
__global__ void scatter_kernel(const float4* __restrict__ rf,
                               const float*  __restrict__ ci,
                               const float*  __restrict__ dm,
                               const int*    __restrict__ src,
                               const int*    __restrict__ dst,
                               int E) {
    int warp = (blockIdx.x * blockDim.x + threadIdx.x) >> 5;
    int lane = threadIdx.x & 31;
    int ebase = warp * 32;
    int e = ebase + lane;

    float m = 0.f, s = 0.f;
    int d = 0;
    if (e < E) {
        m = dm[e];
        if (m != 0.f) {
            d = dst[e];
            s = ci[src[e]] * m;
        }
    }
    unsigned mask = __ballot_sync(0xFFFFFFFFu, m != 0.f);

    int half = lane >> 4;
    int q = lane & 15;

    while (mask) {
        int l0 = __ffs(mask) - 1; mask &= mask - 1;
        int l1 = -1;
        if (mask) { l1 = __ffs(mask) - 1; mask &= mask - 1; }

        int l = half ? l1 : l0;
        int lsafe = (l >= 0) ? l : l0;
        float sv = __shfl_sync(0xFFFFFFFFu, s, lsafe);
        int   dv = __shfl_sync(0xFFFFFFFFu, d, lsafe);

        if (l >= 0) {
            float4 v = rf[(size_t)(ebase + l) * 16 + q];
            v.x *= sv; v.y *= sv; v.z *= sv; v.w *= sv;
            float* p = &g_scratch[(size_t)dv * D + q * 4];
            asm volatile("red.global.add.v4.f32 [%0], {%1, %2, %3, %4};"
                         :: "l"(p), "f"(v.x), "f"(v.y), "f"(v.z), "f"(v.w)
                         : "memory");
        }
    }
}

// ===========================================================================
// HMMA GEMM: out = (g @ W^T) * ci, fp32 via bf16 Karatsuba split:
//   g = ghi + glo, W = Whi + Wlo (bf16);
//   D = ghi@Whi^T + ghi@Wlo^T + glo@Whi^T   (dropped glo@Wlo ~2^-18)
// mma.sync.m16n8k16.row.col.f32.bf16.bf16.f32 + ldmatrix (baseline PTX,
// compiles for plain sm_103 -- no tcgen05 needed).
// Block: 256 thr = 8 warps; tile 128 rows x 64 cols; warp = 16 rows x 64 cols.
// All smem tiles: 128B rows with 16B-chunk XOR swizzle (c ^= row&7) so each
// ldmatrix phase hits 8 distinct 16B banks.
// ===========================================================================
#define SM_WHI 0
#define SM_WLO 8192
#define SM_AHI 16384
#define SM_ALO 32768
#define SM_TOTAL 49152

__device__ __forceinline__ uint32_t smem_u32(const void* p) {
    uint32_t a;
    asm("{ .reg .u64 t; cvta.to.shared.u64 t, %1; cvt.u32.u64 %0, t; }"
        : "=r"(a) : "l"(p));
    return a;
}
__device__ __forceinline__ void ldsm_x4(uint32_t& r0, uint32_t& r1,
                                        uint32_t& r2, uint32_t& r3, uint32_t a) {
    asm volatile("ldmatrix.sync.aligned.m8n8.x4.shared.b16 {%0,%1,%2,%3}, [%4];"
                 : "=r"(r0), "=r"(r1), "=r"(r2), "=r"(r3) : "r"(a));
}
__device__ __forceinline__ void ldsm_x2(uint32_t& r0, uint32_t& r1, uint32_t a) {
    asm volatile("ldmatrix.sync.aligned.m8n8.x2.shared.b16 {%0,%1}, [%2];"
                 : "=r"(r0), "=r"(r1) : "r"(a));
}
__device__ __forceinline__ void mma_bf16(float* d, const uint32_t* a,
                                         uint32_t b0, uint32_t b1) {
    asm volatile("mma.sync.aligned.m16n8k16.row.col.f32.bf16.bf16.f32 "
                 "{%0,%1,%2,%3}, {%4,%5,%6,%7}, {%8,%9}, {%0,%1,%2,%3};"
                 : "+f"(d[0]), "+f"(d[1]), "+f"(d[2]), "+f"(d[3])
                 : "r"(a[0]), "r"(a[1]), "r"(a[2]), "r"(a[3]),
                   "r"(b0), "r"(b1));
}
// split one float4 (4 f32) into packed bf16x2 hi and lo words
__device__ __forceinline__ void split4(const float4& x, uint2& hv, uint2& lv) {
    __nv_bfloat162 h01 = __float22bfloat162_rn(make_float2(x.x, x.y));
    __nv_bfloat162 h23 = __float22bfloat162_rn(make_float2(x.z, x.w));
    float2 f01 = __bfloat1622float2(h01);
    float2 f23 = __bfloat1622float2(h23);
    __nv_bfloat162 l01 = __float22bfloat162_rn(make_float2(x.x - f01.x, x.y - f01.y));
    __nv_bfloat162 l23 = __float22bfloat162_rn(make_float2(x.z - f23.x, x.w - f23.y));
    hv.x = *reinterpret_cast<uint32_t*>(&h01);
    hv.y = *reinterpret_cast<uint32_t*>(&h23);
    lv.x = *reinterpret_cast<uint32_t*>(&l01);
    lv.y = *reinterpret_cast<uint32_t*>(&l23);
}

__global__ void __launch_bounds__(256)
gemm_mma_kernel(const float* __restrict__ W, const float* __restrict__ ci,
                float* __restrict__ out, int N) {
    extern __shared__ __align__(1024) char smem[];
    uint32_t sb = smem_u32(smem);
    int tid = threadIdx.x, w = tid >> 5, lane = tid & 31;
    int row0 = blockIdx.x * 128;

    // ---- convert W -> bf16 hi/lo, swizzled 16B chunks (512 chunks) ----
    #pragma unroll
    for (int i = tid; i < 512; i += 256) {
        int f = i >> 3, c = i & 7;                    // chunk c = 8 floats
        const float4* wp = reinterpret_cast<const float4*>(W) + f * 16 + c * 2;
        float4 x0 = wp[0], x1 = wp[1];
        uint2 h0, l0, h1, l1;
        split4(x0, h0, l0);
        split4(x1, h1, l1);
        uint32_t off = (uint32_t)f * 128 + (uint32_t)((c ^ (f & 7)) << 4);
        *reinterpret_cast<uint4*>(smem + SM_WHI + off) = make_uint4(h0.x, h0.y, h1.x, h1.y);
        *reinterpret_cast<uint4*>(smem + SM_WLO + off) = make_uint4(l0.x, l0.y, l1.x, l1.y);
    }
    // ---- convert g tile [128][64] -> bf16 hi/lo, swizzled (1024 chunks) ----
    #pragma unroll
    for (int i = tid; i < 1024; i += 256) {
        int r = i >> 3, c = i & 7;
        int row = row0 + r;
        float4 x0, x1;
        if (row < N) {
            const float4* gp = reinterpret_cast<const float4*>(g_scratch)
                             + (size_t)row * 16 + c * 2;
            x0 = gp[0]; x1 = gp[1];
        } else {
            x0 = make_float4(0.f, 0.f, 0.f, 0.f);
            x1 = x0;
        }
        uint2 h0, l0, h1, l1;
        split4(x0, h0, l0);
        split4(x1, h1, l1);
        uint32_t off = (uint32_t)r * 128 + (uint32_t)((c ^ (r & 7)) << 4);
        *reinterpret_cast<uint4*>(smem + SM_AHI + off) = make_uint4(h0.x, h0.y, h1.x, h1.y);
        *reinterpret_cast<uint4*>(smem + SM_ALO + off) = make_uint4(l0.x, l0.y, l1.x, l1.y);
    }
    __syncthreads();

    // ---- A fragments for this warp's 16-row stripe (cached in regs) ----
    // ldmatrix.x4 lane plan: lanes 0-7 rows +0..7 (k lo), 8-15 rows +8..15 (k lo),
    // 16-23 rows +0..7 (k hi), 24-31 rows +8..15 (k hi)  => regs = {a0,a1,a2,a3}
    int i8 = lane & 7;
    int halfrow = (lane >> 3) & 1;
    int kpart = lane >> 4;
    int arow = w * 16 + halfrow * 8 + i8;
    uint32_t arow_off = (uint32_t)arow * 128;
    uint32_t ar7 = (uint32_t)(arow & 7);

    uint32_t ahi[4][4], alo[4][4];
    #pragma unroll
    for (int kc = 0; kc < 4; kc++) {
        uint32_t chunk = (uint32_t)(2 * kc + kpart);
        uint32_t aoff = arow_off + ((chunk ^ ar7) << 4);
        ldsm_x4(ahi[kc][0], ahi[kc][1], ahi[kc][2], ahi[kc][3], sb + SM_AHI + aoff);
        ldsm_x4(alo[kc][0], alo[kc][1], alo[kc][2], alo[kc][3], sb + SM_ALO + aoff);
    }

    // ---- B lane plan (x2): lanes 0-7 rows n0..n0+7 (k lo), 8-15 same rows (k hi)
    int bl = lane & 15;
    int bi = bl & 7;
    int bkp = bl >> 3;

    float acc[8][4];
    #pragma unroll
    for (int nb = 0; nb < 8; nb++)
        #pragma unroll
        for (int j = 0; j < 4; j++) acc[nb][j] = 0.f;

    #pragma unroll
    for (int nb = 0; nb < 8; nb++) {
        int n = nb * 8 + bi;
        uint32_t n_off = (uint32_t)n * 128;
        uint32_t n7 = (uint32_t)(n & 7);
        #pragma unroll
        for (int kc = 0; kc < 4; kc++) {
            uint32_t chunk = (uint32_t)(2 * kc + bkp);
            uint32_t boff = n_off + ((chunk ^ n7) << 4);
            uint32_t bh0, bh1, bl0, bl1;
            ldsm_x2(bh0, bh1, sb + SM_WHI + boff);
            ldsm_x2(bl0, bl1, sb + SM_WLO + boff);
            mma_bf16(acc[nb], ahi[kc], bh0, bh1);   // hi*hi
            mma_bf16(acc[nb], ahi[kc], bl0, bl1);   // hi*lo
            mma_bf16(acc[nb], alo[kc], bh0, bh1);   // lo*hi
        }
    }

    // ---- epilogue: scale by ci[row], store float2 per (row, nb) ----
    int group = lane >> 2, tig = lane & 3;
    int rA = row0 + w * 16 + group;       // rows group and group+8
    int rB = rA + 8;
    float cA = (rA < N) ? ci[rA] : 0.f;
    float cB = (rB < N) ? ci[rB] : 0.f;
    #pragma unroll
    for (int nb = 0; nb < 8; nb++) {
        int col = nb * 8 + 2 * tig;
        if (rA < N) {
            float2 v = make_float2(acc[nb][0] * cA, acc[nb][1] * cA);
            *reinterpret_cast<float2*>(&out[(size_t)rA * D + col]) = v;
        }
        if (rB < N) {
            float2 v = make_float2(acc[nb][2] * cB, acc[nb][3] * cB);
            *reinterpret_cast<float2*>(&out[(size_t)rB * D + col]) = v;
        }
    }
}

// ---------------------------------------------------------------------------
// Launch
// Inputs: review_feat [E,64] f32, ci [N,1] f32, W [64,64] f32,
//         drop_mask [E,1] f32, src [E] i32, dst [E] i32.  Output: [N,64] f32
// ---------------------------------------------------------------------------
extern "C" void kernel_launch(void* const* d_in, const int* in_sizes, int n_in,
                              void* d_out, int out_size) {
    const float4* rf  = (const float4*)d_in[0];
    const float*  ci  = (const float*) d_in[1];
    const float*  W   = (const float*) d_in[2];
    const float*  dm  = (const float*) d_in[3];
    const int*    src = (const int*)   d_in[4];
    const int*    dst = (const int*)   d_in[5];
    float* out = (float*)d_out;

    int E = in_sizes[4];
    int N = in_sizes[1];

    // 1. zero scratch accumulator (graph-capturable memset node)
    void* gptr = nullptr;
    cudaGetSymbolAddress(&gptr, g_scratch);
    cudaMemsetAsync(gptr, 0, (size_t)N * D * sizeof(float), 0);

    // 2. warp-cooperative scatter-accumulate (dropout-sparse, REDG.v4)
    int warps = (E + 31) / 32;
    int sblocks = (warps * 32 + 255) / 256;
    scatter_kernel<<<sblocks, 256>>>(rf, ci, dm, src, dst, E);

    // 3. HMMA GEMM (bf16 3-pass split = fp32 accuracy) fused with ci scale
    int gblocks = (N + 127) / 128;
    cudaFuncSetAttribute(gemm_mma_kernel,
                         cudaFuncAttributeMaxDynamicSharedMemorySize, SM_TOTAL);
    gemm_mma_kernel<<<gblocks, 256, SM_TOTAL>>>(W, ci, out, N);
}